// round 16
// baseline (speedup 1.0000x reference)
#include <cuda_runtime.h>
#include <cuda_bf16.h>
#include <cstdint>

// ---------------------------------------------------------------------------
// LocalGlobalCrossAttentionModel — round 16
// softmax over singleton axis == 1.0 -> shapelet/local branch dead code.
// ONE kernel: fused conv1+pool -> conv2 (mma.sync bf16, shifted-view A)
// -> pooled mean partials -> last-block-per-b runs the whole head chain
// (mean -> relu/LN -> v -> attn_out -> mlp) in-block and writes out[b].
// ---------------------------------------------------------------------------

#define B_  64
#define H_  8
#define W1_ 2048
#define W1P 1024
#define C1  16
#define C2  32
#define KK  240              // 15 * 16
#define KP  248              // padded K for B (496B stride, conflict-free)

// per-(b,co,wt) pooled partial sums
__device__ float g_part[B_ * C2 * 8];
// per-b completion counters (self-resetting each launch)
__device__ unsigned int g_cnt[B_];

__device__ __forceinline__ uint32_t smem_u32(const void* p) {
    uint32_t a;
    asm("{ .reg .u64 t; cvta.to.shared.u64 t, %1; cvt.u32.u64 %0, t; }"
        : "=r"(a) : "l"(p));
    return a;
}

#define LDMATRIX_X4(r0, r1, r2, r3, addr)                                   \
    asm volatile("ldmatrix.sync.aligned.m8n8.x4.shared.b16 "                \
                 "{%0, %1, %2, %3}, [%4];"                                  \
                 : "=r"(r0), "=r"(r1), "=r"(r2), "=r"(r3) : "r"(addr))

#define MMA_16816(c, a, b)                                                  \
    asm volatile("mma.sync.aligned.m16n8k16.row.col.f32.bf16.bf16.f32 "     \
                 "{%0, %1, %2, %3}, {%4, %5, %6, %7}, {%8, %9}, "           \
                 "{%0, %1, %2, %3};"                                        \
                 : "+f"((c)[0]), "+f"((c)[1]), "+f"((c)[2]), "+f"((c)[3])   \
                 : "r"((a)[0]), "r"((a)[1]), "r"((a)[2]), "r"((a)[3]),      \
                   "r"((b)[0]), "r"((b)[1]))

// ---------------------------------------------------------------------------
// smem layout (bytes)
// ---------------------------------------------------------------------------
#define A_ROWS   136
#define A_RSTR   48
#define A_PLANE  (A_ROWS * A_RSTR)                  // 6528
#define SA_BYTES (10 * A_PLANE)                     // 65280
#define BS_OFF   SA_BYTES                           // 65280
#define BS_BYTES (C2 * KP * 2)                      // 15872
#define BIAS_OFF (BS_OFF + BS_BYTES)                // 81152
#define RED_OFF  (BIAS_OFF + 128)                   // 81280
#define XS_OFF   (RED_OFF + 1024)                   // 82304
#define XS_ROWF  272                                // floats per x row
#define XS_BYTES (10 * XS_ROWF * 4)                 // 10880
#define FU_SMEM  (XS_OFF + XS_BYTES)                // 93184

// head smem float offsets (aliases sm2; used only after conv phases done)
#define HO_WG   0
#define HO_IPW  2048
#define HO_OW   6144
#define HO_M1W  10240
#define HO_M2W  12288
#define HO_BG   12608
#define HO_GG   12672
#define HO_BEG  12736
#define HO_IPB  12800
#define HO_OB   12864
#define HO_M1B  12928
#define HO_M2B  12960
#define HO_GS   12976
#define HO_A    13008
#define HO_VV   13072
#define HO_AO   13136
#define HO_HH   13200
#define HO_PP   13232
#define HO_RED  13488
// 13492 floats = 53968 bytes < FU_SMEM: fits in the reused buffer

// ---------------------------------------------------------------------------
// Fused kernel. Grid (wt=8, b=64), 256 threads.
// ---------------------------------------------------------------------------
__global__ __launch_bounds__(256) void fused_all_kernel(
    const float* __restrict__ x,
    const float* __restrict__ w1,
    const float* __restrict__ b1,
    const float* __restrict__ w2,
    const float* __restrict__ b2,
    const float* __restrict__ wg,  const float* __restrict__ bg,
    const float* __restrict__ gg,  const float* __restrict__ beg,
    const float* __restrict__ ipw, const float* __restrict__ ipb,
    const float* __restrict__ ow,  const float* __restrict__ ob,
    const float* __restrict__ m1w, const float* __restrict__ m1b,
    const float* __restrict__ m2w, const float* __restrict__ m2b,
    float* __restrict__ out)
{
    extern __shared__ __align__(16) char sm2[];
    __nv_bfloat16* Bs = (__nv_bfloat16*)(sm2 + BS_OFF);
    float* bias_s = (float*)(sm2 + BIAS_OFF);
    float* red    = (float*)(sm2 + RED_OFF);
    float* xs     = (float*)(sm2 + XS_OFF);
    __shared__ unsigned int win_flag;

    int b  = blockIdx.y;
    int wt = blockIdx.x;
    int wbase = wt * 128;
    int tid  = threadIdx.x;
    int wid  = tid >> 5;
    int lane = tid & 31;

    // ---- fill x tile: base col xg0 = 2*wbase-8 (multiple of 4) ----
    int xg0 = 2 * wbase - 8;
    for (int idx = tid; idx < 10 * 68; idx += 256) {
        int p  = idx / 68;
        int q4 = idx - p * 68;
        int row = p - 1;
        float4 v = make_float4(0.f, 0.f, 0.f, 0.f);
        if (row >= 0 && row < H_) {
            int g = xg0 + q4 * 4;
            const float* xr = &x[(b * H_ + row) * W1_];
            if (g >= 0 && g + 3 < W1_) {
                v = *reinterpret_cast<const float4*>(&xr[g]);
            } else {
                float e[4];
#pragma unroll
                for (int k = 0; k < 4; k++)
                    e[k] = (g + k >= 0 && g + k < W1_) ? xr[g + k] : 0.f;
                v = make_float4(e[0], e[1], e[2], e[3]);
            }
        }
        reinterpret_cast<float4*>(&xs[p * XS_ROWF])[q4] = v;
    }
    // ---- zero A planes 0 and 9 (h = -1, 8); A_PLANE = 408 uint4 ----
    for (int idx = tid; idx < 2 * 408; idx += 256) {
        int pl = (idx < 408) ? 0 : 9;
        int j  = idx - (pl ? 408 : 0);
        reinterpret_cast<uint4*>(sm2 + pl * A_PLANE)[j] =
            make_uint4(0, 0, 0, 0);
    }
    // ---- convert conv2 weights into Bs[co][k], k = (kh*5+kw)*16 + ci ----
    for (int idx = tid; idx < C2 * 15 * C1; idx += 256) {
        int ci   = idx & 15;
        int khkw = (idx >> 4) % 15;
        int co   = idx / 240;
        Bs[co * KP + khkw * 16 + ci] =
            __float2bfloat16(w2[(co * 16 + ci) * 15 + khkw]);
    }
    if (tid < 32) bias_s[tid] = b2[tid];

    // ---- per-thread conv1 weights (co = tid&15 -> broadcast LDS) ----
    int co1 = tid & 15;
    int ws  = tid >> 4;
    float wgt[15];
#pragma unroll
    for (int i = 0; i < 15; i++) wgt[i] = __ldg(&w1[co1 * 15 + i]);
    float bias1 = __ldg(&b1[co1]);
    __syncthreads();

    // ---- conv1 + relu + maxpool into planes 1..8 ----
    for (int h = 0; h < 8; h++) {
        char* plane = sm2 + (h + 1) * A_PLANE;
        int r0 = ws * 8;
        float acc[16];
#pragma unroll
        for (int j = 0; j < 16; j++) acc[j] = bias1;
#pragma unroll
        for (int kh = 0; kh < 3; kh++) {
            float buf[24];
            const float4* rp = reinterpret_cast<const float4*>(
                &xs[(h + kh) * XS_ROWF + 16 * ws]);
#pragma unroll
            for (int q = 0; q < 6; q++) {
                float4 f = rp[q];
                buf[4 * q + 0] = f.x; buf[4 * q + 1] = f.y;
                buf[4 * q + 2] = f.z; buf[4 * q + 3] = f.w;
            }
#pragma unroll
            for (int kw = 0; kw < 5; kw++) {
                float w = wgt[kh * 5 + kw];
#pragma unroll
                for (int j = 0; j < 16; j++)
                    acc[j] += w * buf[2 + j + kw];
            }
        }
#pragma unroll
        for (int p = 0; p < 8; p++) {
            int r = r0 + p;
            int w = wbase - 2 + r;
            float v = fmaxf(fmaxf(acc[2 * p], acc[2 * p + 1]), 0.f);
            if (w < 0 || w >= W1P) v = 0.f;
            *reinterpret_cast<__nv_bfloat16*>(plane + r * A_RSTR + co1 * 2) =
                __float2bfloat16(v);
        }
        if (ws < 4) {
            int r = 128 + ws;
            int w = wbase - 2 + r;
            const int lx = 258 + 2 * ws;
            float a0 = bias1, a1 = bias1;
#pragma unroll
            for (int kh = 0; kh < 3; kh++) {
                const float* xr = &xs[(h + kh) * XS_ROWF + lx];
#pragma unroll
                for (int kw = 0; kw < 5; kw++) {
                    float wv = wgt[kh * 5 + kw];
                    a0 += wv * xr[kw];
                    a1 += wv * xr[kw + 1];
                }
            }
            float v = fmaxf(fmaxf(a0, a1), 0.f);
            if (w < 0 || w >= W1P) v = 0.f;
            *reinterpret_cast<__nv_bfloat16*>(plane + r * A_RSTR + co1 * 2) =
                __float2bfloat16(v);
        }
    }
    __syncthreads();

    // ---- conv2 mma phase ----
    uint32_t as_base = smem_u32(sm2);
    uint32_t bs_base = smem_u32(Bs);
    int hg   = wid >> 2;
    int wq   = wid & 3;
    int half = lane >> 4;
    int arow_l = lane & 15;
    int quad = lane >> 3;
    int bw   = lane & 7;
    int tg   = lane & 3;

    float bc[8];
#pragma unroll
    for (int nt = 0; nt < 4; nt++) {
        bc[2 * nt]     = bias_s[nt * 8 + tg * 2];
        bc[2 * nt + 1] = bias_s[nt * 8 + tg * 2 + 1];
    }
    float part[8];
#pragma unroll
    for (int j = 0; j < 8; j++) part[j] = 0.f;

#pragma unroll
    for (int hi = 0; hi < 4; hi++) {
        int h = hg * 4 + hi;
        float acc[2][4][4];
#pragma unroll
        for (int mt = 0; mt < 2; mt++)
#pragma unroll
            for (int nt = 0; nt < 4; nt++)
#pragma unroll
                for (int i = 0; i < 4; i++) acc[mt][nt][i] = 0.f;

#pragma unroll
        for (int s = 0; s < 15; s++) {
            const int kh = s / 5;
            const int kw = s % 5;
            int k0 = s * 16;
            uint32_t a[2][4];
#pragma unroll
            for (int mt = 0; mt < 2; mt++) {
                int mrow = wq * 32 + mt * 16 + arow_l;
                uint32_t addr = as_base + (uint32_t)((h + kh) * A_PLANE
                               + (mrow + kw) * A_RSTR + half * 16);
                LDMATRIX_X4(a[mt][0], a[mt][1], a[mt][2], a[mt][3], addr);
            }
            uint32_t bfr[4][2];
#pragma unroll
            for (int ntp = 0; ntp < 2; ntp++) {
                int nrow = ntp * 16 + (quad >> 1) * 8 + bw;
                uint32_t addr = bs_base + (uint32_t)(nrow * (KP * 2)
                               + (k0 + (quad & 1) * 8) * 2);
                uint32_t r0r, r1r, r2r, r3r;
                LDMATRIX_X4(r0r, r1r, r2r, r3r, addr);
                bfr[2 * ntp][0] = r0r;  bfr[2 * ntp][1] = r1r;
                bfr[2 * ntp + 1][0] = r2r;  bfr[2 * ntp + 1][1] = r3r;
            }
#pragma unroll
            for (int mt = 0; mt < 2; mt++)
#pragma unroll
                for (int nt = 0; nt < 4; nt++)
                    MMA_16816(acc[mt][nt], a[mt], bfr[nt]);
        }

#pragma unroll
        for (int mt = 0; mt < 2; mt++) {
#pragma unroll
            for (int nt = 0; nt < 4; nt++) {
                float v0 = acc[mt][nt][0] + bc[2 * nt];
                float v1 = acc[mt][nt][1] + bc[2 * nt + 1];
                float v2 = acc[mt][nt][2] + bc[2 * nt];
                float v3 = acc[mt][nt][3] + bc[2 * nt + 1];
                float p0 = __shfl_xor_sync(0xffffffffu, v0, 4);
                float p1 = __shfl_xor_sync(0xffffffffu, v1, 4);
                float p2 = __shfl_xor_sync(0xffffffffu, v2, 4);
                float p3 = __shfl_xor_sync(0xffffffffu, v3, 4);
                part[2 * nt]     += fmaxf(fmaxf(v0, p0), 0.f)
                                  + fmaxf(fmaxf(v2, p2), 0.f);
                part[2 * nt + 1] += fmaxf(fmaxf(v1, p1), 0.f)
                                  + fmaxf(fmaxf(v3, p3), 0.f);
            }
        }
    }

#pragma unroll
    for (int j = 0; j < 8; j++) {
        part[j] += __shfl_xor_sync(0xffffffffu, part[j], 8);
        part[j] += __shfl_xor_sync(0xffffffffu, part[j], 16);
    }
    if (lane < 4) {
#pragma unroll
        for (int nt = 0; nt < 4; nt++) {
            red[wid * 32 + nt * 8 + lane * 2]     = part[2 * nt];
            red[wid * 32 + nt * 8 + lane * 2 + 1] = part[2 * nt + 1];
        }
    }
    __syncthreads();
    if (tid < 32) {
        float tot = 0.f;
#pragma unroll
        for (int wdi = 0; wdi < 8; wdi++) tot += red[wdi * 32 + tid];
        g_part[(b * C2 + tid) * 8 + wt] = tot;
    }

    // ---- completion: last block of this b runs the head chain ----
    __syncthreads();
    if (tid == 0) {
        __threadfence();                       // publish g_part
        unsigned int r = atomicAdd(&g_cnt[b], 1u);
        win_flag = (r == 7u);
        if (r == 7u) g_cnt[b] = 0u;            // reset for next replay
    }
    __syncthreads();
    if (!win_flag) return;
    __threadfence();                           // acquire other blocks' g_part

    // ================= head chain (reuses sm2 as float scratch) ===========
    float* sh = (float*)sm2;
    int t = tid & 63;
    int q = tid >> 6;

    float gsv = 0.f;
    if (tid < 32) {
        float s = 0.f;
#pragma unroll
        for (int i = 0; i < 8; i++) s += g_part[(b * C2 + tid) * 8 + i];
        gsv = s * (1.0f / 4096.0f);
    }

#define CP4(off, src, n4)                                                   \
    for (int i = tid; i < (n4); i += 256)                                   \
        reinterpret_cast<float4*>(sh + (off))[i] =                          \
            reinterpret_cast<const float4*>(src)[i];
    CP4(HO_WG,  wg,             512)
    CP4(HO_IPW, ipw + 128 * 64, 1024)
    CP4(HO_OW,  ow,             1024)
    CP4(HO_M1W, m1w,            512)
    CP4(HO_M2W, m2w,            80)
    CP4(HO_BG,  bg,  16)
    CP4(HO_GG,  gg,  16)
    CP4(HO_BEG, beg, 16)
    CP4(HO_IPB, ipb + 128, 16)
    CP4(HO_OB,  ob,  16)
    CP4(HO_M1B, m1b, 8)
#undef CP4
    if (tid < 10) sh[HO_M2B + tid] = m2b[tid];
    __syncthreads();                 // sm2 fully repurposed
    if (tid < 32) sh[HO_GS + tid] = gsv;
    __syncthreads();

    float* pp = sh + HO_PP;

    {
        float s = 0.f;
#pragma unroll
        for (int i = 0; i < 8; i++) {
            int e = q * 8 + i;
            s += sh[HO_GS + e] * sh[HO_WG + e * 64 + t];
        }
        pp[q * 64 + t] = s;
    }
    __syncthreads();
    float pre = 0.f;
    if (tid < 64) {
        pre = pp[t] + pp[64 + t] + pp[128 + t] + pp[192 + t] + sh[HO_BG + t];
        pre = fmaxf(pre, 0.f);
    }
    if (tid < 64) {
        float s = pre;
#pragma unroll
        for (int o = 16; o > 0; o >>= 1) s += __shfl_xor_sync(0xffffffffu, s, o);
        if (lane == 0) sh[HO_RED + wid] = s;
    }
    __syncthreads();
    float mean = (sh[HO_RED] + sh[HO_RED + 1]) * (1.0f / 64.0f);
    if (tid < 64) {
        float d = pre - mean;
        float s = d * d;
#pragma unroll
        for (int o = 16; o > 0; o >>= 1) s += __shfl_xor_sync(0xffffffffu, s, o);
        if (lane == 0) sh[HO_RED + 2 + wid] = s;
    }
    __syncthreads();
    if (tid < 64) {
        float var = (sh[HO_RED + 2] + sh[HO_RED + 3]) * (1.0f / 64.0f);
        sh[HO_A + t] = (pre - mean) * rsqrtf(var + 1e-5f) * sh[HO_GG + t]
                       + sh[HO_BEG + t];
    }
    __syncthreads();

    {
        float s = 0.f;
#pragma unroll
        for (int i = 0; i < 16; i++) {
            int e = q * 16 + i;
            s += sh[HO_A + e] * sh[HO_IPW + t * 64 + e];
        }
        pp[q * 64 + t] = s;
    }
    __syncthreads();
    if (tid < 64)
        sh[HO_VV + t] = pp[t] + pp[64 + t] + pp[128 + t] + pp[192 + t]
                        + sh[HO_IPB + t];
    __syncthreads();

    {
        float s = 0.f;
#pragma unroll
        for (int i = 0; i < 16; i++) {
            int j = q * 16 + i;
            s += sh[HO_VV + j] * sh[HO_OW + t * 64 + j];
        }
        pp[q * 64 + t] = s;
    }
    __syncthreads();
    if (tid < 64)
        sh[HO_AO + t] = pp[t] + pp[64 + t] + pp[128 + t] + pp[192 + t]
                        + sh[HO_OB + t];
    __syncthreads();

    {
        int t32 = tid & 31, q2 = wid;
        float s = 0.f;
#pragma unroll
        for (int i = 0; i < 8; i++) {
            int e = q2 * 8 + i;
            s += sh[HO_AO + e] * sh[HO_M1W + e * 32 + t32];
        }
        pp[q2 * 32 + t32] = s;
    }
    __syncthreads();
    if (tid < 32) {
        float s = sh[HO_M1B + tid];
#pragma unroll
        for (int g2 = 0; g2 < 8; g2++) s += pp[g2 * 32 + tid];
        sh[HO_HH + tid] = fmaxf(s, 0.f);
    }
    __syncthreads();

    if (tid < 10) {
        float o = sh[HO_M2B + tid];
#pragma unroll
        for (int m = 0; m < 32; m++)
            o += sh[HO_HH + m] * sh[HO_M2W + m * 10 + tid];
        out[b * 10 + tid] = o;
    }
}

// ---------------------------------------------------------------------------
extern "C" void kernel_launch(void* const* d_in, const int* in_sizes, int n_in,
                              void* d_out, int out_size)
{
    const float* x    = (const float*)d_in[0];
    const float* c1w  = (const float*)d_in[6];
    const float* c1b  = (const float*)d_in[7];
    const float* c2w  = (const float*)d_in[8];
    const float* c2b  = (const float*)d_in[9];
    const float* wg   = (const float*)d_in[10];
    const float* bg   = (const float*)d_in[11];
    const float* gg   = (const float*)d_in[12];
    const float* beg  = (const float*)d_in[13];
    const float* ipw  = (const float*)d_in[14];
    const float* ipb  = (const float*)d_in[15];
    const float* ow   = (const float*)d_in[16];
    const float* ob   = (const float*)d_in[17];
    const float* m1w  = (const float*)d_in[18];
    const float* m1b  = (const float*)d_in[19];
    const float* m2w  = (const float*)d_in[20];
    const float* m2b  = (const float*)d_in[21];
    float* out = (float*)d_out;

    cudaFuncSetAttribute(fused_all_kernel,
                         cudaFuncAttributeMaxDynamicSharedMemorySize, FU_SMEM);

    dim3 g1(8, B_);
    fused_all_kernel<<<g1, 256, FU_SMEM>>>(
        x, c1w, c1b, c2w, c2b,
        wg, bg, gg, beg, ipw, ipb, ow, ob, m1w, m1b, m2w, m2b, out);
}